// round 5
// baseline (speedup 1.0000x reference)
#include <cuda_runtime.h>
#include <cuda_fp16.h>

// GraphSAGE 2-layer encoder, restructured:
//   y = h@Wl (fp16), z = h@Wr + b (fp32), out[i] = inv[i]*sum_{j in N(i)} y[j] + z[i]
// Layer-1 agg + layer-2 GEMM fused; GEMM1 runs concurrently with the CSR
// histogram via block-range fusion (no extra launch, no stream forks).

#define NMAX 100000
#define EMAX 1600000
#define F 64

__device__ __align__(16) __half g_ya[NMAX * F];   // layer-1 y (fp16)
__device__ __align__(16) __half g_yb[NMAX * F];   // layer-2 y (fp16)
__device__ __align__(16) float  g_z1[NMAX * F];
__device__ __align__(16) float  g_z2[NMAX * F];
__device__ float g_invdeg[NMAX];
__device__ int   g_cnt[NMAX];        // zero-init at load; re-zeroed by k_agg2
__device__ int   g_rowptr[NMAX + 1];
__device__ int   g_pos[EMAX];        // per-edge within-row position
__device__ int   g_col[EMAX];
__device__ int   g_part[128];

// ------------------------------ fused histogram (CSR pass 1) + layer-1 GEMM
// blocks [0, HB): hist -> g_cnt, g_pos.  blocks [HB, ...): dual GEMM
// ya = X @ Wl (fp16) ; z1 = X @ Wr + b (fp32)
__global__ __launch_bounds__(256) void k_histgemm(const int* __restrict__ dst, int E, int HB,
                                                  const float* __restrict__ X,
                                                  const float* __restrict__ Wl,
                                                  const float* __restrict__ Wr,
                                                  const float* __restrict__ B,
                                                  int n) {
    if (blockIdx.x < (unsigned)HB) {
        int e = blockIdx.x * 256 + threadIdx.x;
        if (e < E) {
            int d = dst[e];
            g_pos[e] = atomicAdd(&g_cnt[d], 1);
        }
        return;
    }

    __shared__ float xs[64 * 68];
    __shared__ float wls[64 * 64];
    __shared__ float wrs[64 * 64];
    __shared__ float bs[64];

    int tid  = threadIdx.x;
    int row0 = (blockIdx.x - HB) * 64;

    for (int t = tid; t < 1024; t += 256) {
        ((float4*)wls)[t] = ((const float4*)Wl)[t];
        ((float4*)wrs)[t] = ((const float4*)Wr)[t];
    }
    if (tid < 64) bs[tid] = B[tid];
    for (int t = tid; t < 1024; t += 256) {
        int r = t >> 4, c4 = (t & 15) << 2;
        int g = row0 + r;
        float4 v = make_float4(0.f, 0.f, 0.f, 0.f);
        if (g < n) v = *(const float4*)&X[g * 64 + c4];
        xs[r * 68 + c4 + 0] = v.x; xs[r * 68 + c4 + 1] = v.y;
        xs[r * 68 + c4 + 2] = v.z; xs[r * 68 + c4 + 3] = v.w;
    }
    __syncthreads();

    int tx = tid & 15, ty = tid >> 4;
    int c = tx << 2, r = ty << 2;

    float4 ay[4], az[4];
    #pragma unroll
    for (int i = 0; i < 4; i++) {
        ay[i] = make_float4(0.f, 0.f, 0.f, 0.f);
        az[i] = make_float4(0.f, 0.f, 0.f, 0.f);
    }
    #pragma unroll 4
    for (int k = 0; k < 64; ++k) {
        float4 wl4 = *(const float4*)&wls[k * 64 + c];
        float4 wr4 = *(const float4*)&wrs[k * 64 + c];
        #pragma unroll
        for (int i = 0; i < 4; i++) {
            float xv = xs[(r + i) * 68 + k];
            ay[i].x += xv * wl4.x; ay[i].y += xv * wl4.y;
            ay[i].z += xv * wl4.z; ay[i].w += xv * wl4.w;
            az[i].x += xv * wr4.x; az[i].y += xv * wr4.y;
            az[i].z += xv * wr4.z; az[i].w += xv * wr4.w;
        }
    }

    float4 bb = make_float4(bs[c], bs[c + 1], bs[c + 2], bs[c + 3]);
    #pragma unroll
    for (int i = 0; i < 4; i++) {
        int g = row0 + r + i;
        if (g < n) {
            *(__half2*)&g_ya[g * 64 + c]     = __floats2half2_rn(ay[i].x, ay[i].y);
            *(__half2*)&g_ya[g * 64 + c + 2] = __floats2half2_rn(ay[i].z, ay[i].w);
            float4 zz = az[i];
            zz.x += bb.x; zz.y += bb.y; zz.z += bb.z; zz.w += bb.w;
            *(float4*)&g_z1[g * 64 + c] = zz;
        }
    }
}

// pass 1: per-1024-chunk exclusive scan; emit chunk totals; invdeg
__global__ void k_scan1(int n) {
    __shared__ int sh[1024];
    int tid = threadIdx.x;
    int i = blockIdx.x * 1024 + tid;
    int v = (i < n) ? g_cnt[i] : 0;
    sh[tid] = v;
    __syncthreads();
    #pragma unroll
    for (int off = 1; off < 1024; off <<= 1) {
        int t = (tid >= off) ? sh[tid - off] : 0;
        __syncthreads();
        sh[tid] += t;
        __syncthreads();
    }
    if (i < n) {
        g_rowptr[i] = sh[tid] - v;               // chunk-local exclusive
        g_invdeg[i] = 1.0f / (float)max(v, 1);
    }
    if (tid == 1023) g_part[blockIdx.x] = sh[1023];
}

// pass 2+3 fused: every block redundantly scans chunk totals, adds offsets
__global__ __launch_bounds__(256) void k_scan23(int n, int E, int nb) {
    __shared__ int sh[128], sh2[128];
    int tid = threadIdx.x;
    if (tid < 128) sh[tid] = (tid < nb) ? g_part[tid] : 0;
    __syncthreads();
    int orig = (tid < 128) ? sh[tid] : 0;
    #pragma unroll
    for (int off = 1; off < 128; off <<= 1) {
        int t = 0;
        if (tid < 128 && tid >= off) t = sh[tid - off];
        __syncthreads();
        if (tid < 128) sh[tid] += t;
        __syncthreads();
    }
    if (tid < 128) sh2[tid] = sh[tid] - orig;    // exclusive chunk offsets
    __syncthreads();
    int i = blockIdx.x * blockDim.x + tid;
    if (i < n) g_rowptr[i] += sh2[i >> 10];
    if (i == 0) g_rowptr[n] = E;
}

// atomic-free scatter: position was precomputed in the hist pass
__global__ void k_scatter(const int* __restrict__ src, const int* __restrict__ dst, int E) {
    int e = blockIdx.x * blockDim.x + threadIdx.x;
    if (e < E) {
        int d = dst[e];
        g_col[g_rowptr[d] + g_pos[e]] = src[e];
    }
}

// -------------------------------- fused layer-1 aggregate + layer-2 dual GEMM
__global__ __launch_bounds__(256) void k_fused(const float* __restrict__ Wl,
                                               const float* __restrict__ Wr,
                                               const float* __restrict__ B,
                                               int n) {
    __shared__ float xs[64 * 68];
    __shared__ float wls[64 * 64];
    __shared__ float wrs[64 * 64];
    __shared__ float bs[64];

    int tid  = threadIdx.x;
    int row0 = blockIdx.x * 64;
    int lane = tid & 31, w = tid >> 5;

    for (int t = tid; t < 1024; t += 256) {
        ((float4*)wls)[t] = ((const float4*)Wl)[t];
        ((float4*)wrs)[t] = ((const float4*)Wr)[t];
    }
    if (tid < 64) bs[tid] = B[tid];

    // phase 1: warp per node, lane owns dims (2*lane, 2*lane+1); 8-wide MLP
    const __half2* Y = (const __half2*)g_ya;
    #pragma unroll 1
    for (int pass = 0; pass < 8; ++pass) {
        int nl   = pass * 8 + w;
        int node = row0 + nl;
        float hx = 0.f, hy = 0.f;
        if (node < n) {
            int s = g_rowptr[node], e = g_rowptr[node + 1];
            float ax[8], ayv[8];
            #pragma unroll
            for (int u = 0; u < 8; ++u) { ax[u] = 0.f; ayv[u] = 0.f; }
            int i = s;
            for (; i + 7 < e; i += 8) {
                #pragma unroll
                for (int u = 0; u < 8; ++u) {
                    float2 v = __half22float2(Y[g_col[i + u] * 32 + lane]);
                    ax[u] += v.x; ayv[u] += v.y;
                }
            }
            for (; i < e; ++i) {
                float2 v = __half22float2(Y[g_col[i] * 32 + lane]);
                ax[0] += v.x; ayv[0] += v.y;
            }
            float sx = ((ax[0]+ax[1])+(ax[2]+ax[3]))+((ax[4]+ax[5])+(ax[6]+ax[7]));
            float sy = ((ayv[0]+ayv[1])+(ayv[2]+ayv[3]))+((ayv[4]+ayv[5])+(ayv[6]+ayv[7]));
            float inv = g_invdeg[node];
            float2 z  = *(const float2*)&g_z1[node * 64 + 2 * lane];
            hx = fmaxf(sx * inv + z.x, 0.f);
            hy = fmaxf(sy * inv + z.y, 0.f);
        }
        xs[nl * 68 + 2 * lane]     = hx;
        xs[nl * 68 + 2 * lane + 1] = hy;
    }
    __syncthreads();

    // phase 2: dual GEMM from smem
    int tx = tid & 15, ty = tid >> 4;
    int c = tx << 2, r = ty << 2;

    float4 ay[4], az[4];
    #pragma unroll
    for (int i = 0; i < 4; i++) {
        ay[i] = make_float4(0.f, 0.f, 0.f, 0.f);
        az[i] = make_float4(0.f, 0.f, 0.f, 0.f);
    }
    #pragma unroll 4
    for (int k = 0; k < 64; ++k) {
        float4 wl4 = *(const float4*)&wls[k * 64 + c];
        float4 wr4 = *(const float4*)&wrs[k * 64 + c];
        #pragma unroll
        for (int i = 0; i < 4; i++) {
            float xv = xs[(r + i) * 68 + k];
            ay[i].x += xv * wl4.x; ay[i].y += xv * wl4.y;
            ay[i].z += xv * wl4.z; ay[i].w += xv * wl4.w;
            az[i].x += xv * wr4.x; az[i].y += xv * wr4.y;
            az[i].z += xv * wr4.z; az[i].w += xv * wr4.w;
        }
    }

    float4 bb = make_float4(bs[c], bs[c + 1], bs[c + 2], bs[c + 3]);
    #pragma unroll
    for (int i = 0; i < 4; i++) {
        int g = row0 + r + i;
        if (g < n) {
            *(__half2*)&g_yb[g * 64 + c]     = __floats2half2_rn(ay[i].x, ay[i].y);
            *(__half2*)&g_yb[g * 64 + c + 2] = __floats2half2_rn(ay[i].z, ay[i].w);
            float4 zz = az[i];
            zz.x += bb.x; zz.y += bb.y; zz.z += bb.z; zz.w += bb.w;
            *(float4*)&g_z2[g * 64 + c] = zz;
        }
    }
}

// --------------------------------------------------------- final aggregate
__global__ __launch_bounds__(256) void k_agg2(float* __restrict__ O, int n) {
    int tid  = threadIdx.x;
    int lane = tid & 31, w = tid >> 5;
    int node = blockIdx.x * 8 + w;

    if (tid < 8) {
        int nn = blockIdx.x * 8 + tid;
        if (nn < n) g_cnt[nn] = 0;      // counters clean for next graph replay
    }
    if (node >= n) return;

    const __half2* Y = (const __half2*)g_yb;
    int s = g_rowptr[node], e = g_rowptr[node + 1];
    float ax[8], ayv[8];
    #pragma unroll
    for (int u = 0; u < 8; ++u) { ax[u] = 0.f; ayv[u] = 0.f; }
    int i = s;
    for (; i + 7 < e; i += 8) {
        #pragma unroll
        for (int u = 0; u < 8; ++u) {
            float2 v = __half22float2(Y[g_col[i + u] * 32 + lane]);
            ax[u] += v.x; ayv[u] += v.y;
        }
    }
    for (; i < e; ++i) {
        float2 v = __half22float2(Y[g_col[i] * 32 + lane]);
        ax[0] += v.x; ayv[0] += v.y;
    }
    float sx = ((ax[0]+ax[1])+(ax[2]+ax[3]))+((ax[4]+ax[5])+(ax[6]+ax[7]));
    float sy = ((ayv[0]+ayv[1])+(ayv[2]+ayv[3]))+((ayv[4]+ayv[5])+(ayv[6]+ayv[7]));
    float inv = g_invdeg[node];
    float2 z  = *(const float2*)&g_z2[node * 64 + 2 * lane];
    float2 o;
    o.x = sx * inv + z.x;
    o.y = sy * inv + z.y;
    *(float2*)&O[node * 64 + 2 * lane] = o;
}

// ------------------------------------------------------------------- launch
extern "C" void kernel_launch(void* const* d_in, const int* in_sizes, int n_in,
                              void* d_out, int out_size) {
    const float* x   = (const float*)d_in[0];
    const int*   ei  = (const int*)d_in[1];
    const float* w1l = (const float*)d_in[2];
    const float* b1l = (const float*)d_in[3];
    const float* w1r = (const float*)d_in[4];
    const float* w2l = (const float*)d_in[5];
    const float* b2l = (const float*)d_in[6];
    const float* w2r = (const float*)d_in[7];
    float* out = (float*)d_out;

    int n = in_sizes[0] / F;
    int E = in_sizes[1] / 2;
    const int* src = ei;
    const int* dst = ei + E;

    int nb1024 = (n + 1023) / 1024;
    int HB = (E + 255) / 256;            // hist blocks
    int GB = (n + 63) / 64;              // gemm blocks

    k_histgemm<<<HB + GB, 256>>>(dst, E, HB, x, w1l, w1r, b1l, n);
    k_scan1   <<<nb1024, 1024>>>(n);
    k_scan23  <<<(n + 255) / 256, 256>>>(n, E, nb1024);
    k_scatter <<<(E + 255) / 256, 256>>>(src, dst, E);

    k_fused <<<(n + 63) / 64, 256>>>(w2l, w2r, b2l, n);
    k_agg2  <<<(n + 7) / 8, 256>>>(out, n);
}

// round 8
// speedup vs baseline: 1.4217x; 1.4217x over previous
#include <cuda_runtime.h>
#include <cuda_fp16.h>
#include <cstdint>

// GraphSAGE 2-layer encoder.
//   y = h@Wl (fp16), z = h@Wr + b (fp32), out[i] = inv[i]*sum_{j in N(i)} y[j] + z[i]
// GEMMs on tensor cores (HMMA m16n8k16, fp32 accum). Layer-1 agg + layer-2
// GEMM fused; layer-1 GEMM overlapped with CSR histogram via block ranges.

#define NMAX 100000
#define EMAX 1600000
#define F 64
#define TS 72   // smem row stride in halves (144B -> conflict-free LDSM)

__device__ __align__(16) __half g_ya[NMAX * F];
__device__ __align__(16) __half g_yb[NMAX * F];
__device__ __align__(16) float  g_z1[NMAX * F];
__device__ __align__(16) float  g_z2[NMAX * F];
__device__ float g_invdeg[NMAX];
__device__ int   g_cnt[NMAX];        // zero-init at load; re-zeroed by k_agg2
__device__ int   g_rowptr[NMAX + 1];
__device__ int   g_pos[EMAX];
__device__ int   g_col[EMAX];
__device__ int   g_part[128];

// ---------------------------------------------------------------- MMA bits
__device__ __forceinline__ unsigned smem_u32(const void* p) {
    return (unsigned)__cvta_generic_to_shared(p);
}
__device__ __forceinline__ void ldsm_x4(unsigned& a0, unsigned& a1,
                                        unsigned& a2, unsigned& a3, unsigned addr) {
    asm volatile("ldmatrix.sync.aligned.m8n8.x4.shared.b16 {%0,%1,%2,%3}, [%4];"
                 : "=r"(a0), "=r"(a1), "=r"(a2), "=r"(a3) : "r"(addr));
}
__device__ __forceinline__ void ldsm_x2t(unsigned& b0, unsigned& b1, unsigned addr) {
    asm volatile("ldmatrix.sync.aligned.m8n8.x2.trans.shared.b16 {%0,%1}, [%2];"
                 : "=r"(b0), "=r"(b1) : "r"(addr));
}
__device__ __forceinline__ void mma16816(float* d, unsigned a0, unsigned a1,
                                         unsigned a2, unsigned a3,
                                         unsigned b0, unsigned b1) {
    asm volatile("mma.sync.aligned.m16n8k16.row.col.f32.f16.f16.f32 "
                 "{%0,%1,%2,%3}, {%4,%5,%6,%7}, {%8,%9}, {%0,%1,%2,%3};"
                 : "+f"(d[0]), "+f"(d[1]), "+f"(d[2]), "+f"(d[3])
                 : "r"(a0), "r"(a1), "r"(a2), "r"(a3), "r"(b0), "r"(b1));
}

// Dual GEMM on a 64-row tile: Y = A@Wl (fp16 out), Z = A@Wr + b (fp32 out).
// A,Wl,Wr are fp16 smem tiles [64 x TS]; 256 threads = 8 warps.
// warp w: rows 16*(w&3), cols 32*(w>>2)..+32.
__device__ __forceinline__ void mma_dual(const __half* xs, const __half* wls,
                                         const __half* wrs, const float* bs,
                                         __half* Yg, float* Zg, int row0, int n,
                                         int tid) {
    int w = tid >> 5, l = tid & 31;
    int m0 = (w & 3) * 16;
    int nb = (w >> 2) * 32;

    float acc0[4][4], acc1[4][4];
    #pragma unroll
    for (int j = 0; j < 4; ++j)
        #pragma unroll
        for (int q = 0; q < 4; ++q) { acc0[j][q] = 0.f; acc1[j][q] = 0.f; }

    int ag = l >> 3, ar = l & 7;
    int arow = m0 + (ag & 1) * 8 + ar;
    int acol = (ag >> 1) * 8;
    int br   = (l & 7) + ((l >> 3) & 1) * 8;

    #pragma unroll
    for (int kc = 0; kc < 4; ++kc) {
        int k0 = kc * 16;
        unsigned a0, a1, a2, a3;
        ldsm_x4(a0, a1, a2, a3, smem_u32(&xs[arow * TS + k0 + acol]));
        #pragma unroll
        for (int j = 0; j < 4; ++j) {
            int n0 = nb + j * 8;
            unsigned b0, b1, c0, c1;
            ldsm_x2t(b0, b1, smem_u32(&wls[(k0 + br) * TS + n0]));
            mma16816(acc0[j], a0, a1, a2, a3, b0, b1);
            ldsm_x2t(c0, c1, smem_u32(&wrs[(k0 + br) * TS + n0]));
            mma16816(acc1[j], a0, a1, a2, a3, c0, c1);
        }
    }

    int tr = l >> 2, tc = (l & 3) * 2;
    #pragma unroll
    for (int j = 0; j < 4; ++j) {
        int gc = nb + j * 8 + tc;
        float bx = bs[gc], by = bs[gc + 1];
        #pragma unroll
        for (int h = 0; h < 2; ++h) {
            int gr = row0 + m0 + tr + h * 8;
            if (gr < n) {
                *(__half2*)&Yg[gr * 64 + gc] =
                    __floats2half2_rn(acc0[j][h * 2], acc0[j][h * 2 + 1]);
                *(float2*)&Zg[gr * 64 + gc] =
                    make_float2(acc1[j][h * 2] + bx, acc1[j][h * 2 + 1] + by);
            }
        }
    }
}

// ------------------------------ fused histogram (CSR pass 1) + layer-1 GEMM
__global__ __launch_bounds__(256) void k_histgemm(const int* __restrict__ dst, int E, int HB,
                                                  const float* __restrict__ X,
                                                  const float* __restrict__ Wl,
                                                  const float* __restrict__ Wr,
                                                  const float* __restrict__ B,
                                                  int n) {
    if (blockIdx.x < (unsigned)HB) {
        int e = blockIdx.x * 256 + threadIdx.x;
        if (e < E) {
            int d = dst[e];
            g_pos[e] = atomicAdd(&g_cnt[d], 1);
        }
        return;
    }

    __shared__ __half xs[64 * TS];
    __shared__ __half wls[64 * TS];
    __shared__ __half wrs[64 * TS];
    __shared__ float  bs[64];

    int tid  = threadIdx.x;
    int row0 = ((int)blockIdx.x - HB) * 64;

    for (int t = tid; t < 1024; t += 256) {
        int r = t >> 4, c4 = (t & 15) << 2;
        float4 wl = ((const float4*)Wl)[t];
        float4 wr = ((const float4*)Wr)[t];
        *(__half2*)&wls[r * TS + c4]     = __floats2half2_rn(wl.x, wl.y);
        *(__half2*)&wls[r * TS + c4 + 2] = __floats2half2_rn(wl.z, wl.w);
        *(__half2*)&wrs[r * TS + c4]     = __floats2half2_rn(wr.x, wr.y);
        *(__half2*)&wrs[r * TS + c4 + 2] = __floats2half2_rn(wr.z, wr.w);

        int g = row0 + r;
        float4 v = make_float4(0.f, 0.f, 0.f, 0.f);
        if (g < n) v = *(const float4*)&X[g * 64 + c4];
        *(__half2*)&xs[r * TS + c4]     = __floats2half2_rn(v.x, v.y);
        *(__half2*)&xs[r * TS + c4 + 2] = __floats2half2_rn(v.z, v.w);
    }
    if (tid < 64) bs[tid] = B[tid];
    __syncthreads();

    mma_dual(xs, wls, wrs, bs, g_ya, g_z1, row0, n, tid);
}

// pass 1: per-1024-chunk exclusive scan; chunk totals; invdeg
__global__ void k_scan1(int n) {
    __shared__ int sh[1024];
    int tid = threadIdx.x;
    int i = blockIdx.x * 1024 + tid;
    int v = (i < n) ? g_cnt[i] : 0;
    sh[tid] = v;
    __syncthreads();
    #pragma unroll
    for (int off = 1; off < 1024; off <<= 1) {
        int t = (tid >= off) ? sh[tid - off] : 0;
        __syncthreads();
        sh[tid] += t;
        __syncthreads();
    }
    if (i < n) {
        g_rowptr[i] = sh[tid] - v;
        g_invdeg[i] = 1.0f / (float)max(v, 1);
    }
    if (tid == 1023) g_part[blockIdx.x] = sh[1023];
}

// pass 2+3 fused
__global__ __launch_bounds__(256) void k_scan23(int n, int E, int nb) {
    __shared__ int sh[128], sh2[128];
    int tid = threadIdx.x;
    if (tid < 128) sh[tid] = (tid < nb) ? g_part[tid] : 0;
    __syncthreads();
    int orig = (tid < 128) ? sh[tid] : 0;
    #pragma unroll
    for (int off = 1; off < 128; off <<= 1) {
        int t = 0;
        if (tid < 128 && tid >= off) t = sh[tid - off];
        __syncthreads();
        if (tid < 128) sh[tid] += t;
        __syncthreads();
    }
    if (tid < 128) sh2[tid] = sh[tid] - orig;
    __syncthreads();
    int i = blockIdx.x * blockDim.x + tid;
    if (i < n) g_rowptr[i] += sh2[i >> 10];
    if (i == 0) g_rowptr[n] = E;
}

// atomic-free scatter
__global__ void k_scatter(const int* __restrict__ src, const int* __restrict__ dst, int E) {
    int e = blockIdx.x * blockDim.x + threadIdx.x;
    if (e < E) {
        int d = dst[e];
        g_col[g_rowptr[d] + g_pos[e]] = src[e];
    }
}

// -------------------------------- fused layer-1 aggregate + layer-2 GEMM
__global__ __launch_bounds__(256) void k_fused(const float* __restrict__ Wl,
                                               const float* __restrict__ Wr,
                                               const float* __restrict__ B,
                                               int n) {
    __shared__ __half xs[64 * TS];
    __shared__ __half wls[64 * TS];
    __shared__ __half wrs[64 * TS];
    __shared__ float  bs[64];

    int tid  = threadIdx.x;
    int row0 = blockIdx.x * 64;
    int lane = tid & 31, w = tid >> 5;

    for (int t = tid; t < 1024; t += 256) {
        int r = t >> 4, c4 = (t & 15) << 2;
        float4 wl = ((const float4*)Wl)[t];
        float4 wr = ((const float4*)Wr)[t];
        *(__half2*)&wls[r * TS + c4]     = __floats2half2_rn(wl.x, wl.y);
        *(__half2*)&wls[r * TS + c4 + 2] = __floats2half2_rn(wl.z, wl.w);
        *(__half2*)&wrs[r * TS + c4]     = __floats2half2_rn(wr.x, wr.y);
        *(__half2*)&wrs[r * TS + c4 + 2] = __floats2half2_rn(wr.z, wr.w);
    }
    if (tid < 64) bs[tid] = B[tid];

    // phase 1: warp per node; lane owns dims (2*lane, 2*lane+1); 8-wide MLP
    const __half2* Y = (const __half2*)g_ya;
    #pragma unroll 1
    for (int pass = 0; pass < 8; ++pass) {
        int nl   = pass * 8 + w;
        int node = row0 + nl;
        float hx = 0.f, hy = 0.f;
        if (node < n) {
            int s = g_rowptr[node], e = g_rowptr[node + 1];
            float sxa[8], sya[8];
            #pragma unroll
            for (int u = 0; u < 8; ++u) { sxa[u] = 0.f; sya[u] = 0.f; }
            int i = s;
            for (; i + 7 < e; i += 8) {
                #pragma unroll
                for (int u = 0; u < 8; ++u) {
                    float2 v = __half22float2(Y[g_col[i + u] * 32 + lane]);
                    sxa[u] += v.x; sya[u] += v.y;
                }
            }
            for (; i < e; ++i) {
                float2 v = __half22float2(Y[g_col[i] * 32 + lane]);
                sxa[0] += v.x; sya[0] += v.y;
            }
            float sx = ((sxa[0]+sxa[1])+(sxa[2]+sxa[3]))+((sxa[4]+sxa[5])+(sxa[6]+sxa[7]));
            float sy = ((sya[0]+sya[1])+(sya[2]+sya[3]))+((sya[4]+sya[5])+(sya[6]+sya[7]));
            float inv = g_invdeg[node];
            float2 z  = *(const float2*)&g_z1[node * 64 + 2 * lane];
            hx = fmaxf(sx * inv + z.x, 0.f);
            hy = fmaxf(sy * inv + z.y, 0.f);
        }
        *(__half2*)&xs[nl * TS + 2 * lane] = __floats2half2_rn(hx, hy);
    }
    __syncthreads();

    mma_dual(xs, wls, wrs, bs, g_yb, g_z2, row0, n, tid);
}

// --------------------------------------------------------- final aggregate
__global__ __launch_bounds__(256) void k_agg2(float* __restrict__ Og, int n) {
    int tid  = threadIdx.x;
    int lane = tid & 31, w = tid >> 5;
    int node = blockIdx.x * 8 + w;

    if (tid < 8) {
        int nn = blockIdx.x * 8 + tid;
        if (nn < n) g_cnt[nn] = 0;      // counters clean for next graph replay
    }
    if (node >= n) return;

    const __half2* Y = (const __half2*)g_yb;
    int s = g_rowptr[node], e = g_rowptr[node + 1];
    float sxa[8], sya[8];
    #pragma unroll
    for (int u = 0; u < 8; ++u) { sxa[u] = 0.f; sya[u] = 0.f; }
    int i = s;
    for (; i + 7 < e; i += 8) {
        #pragma unroll
        for (int u = 0; u < 8; ++u) {
            float2 v = __half22float2(Y[g_col[i + u] * 32 + lane]);
            sxa[u] += v.x; sya[u] += v.y;
        }
    }
    for (; i < e; ++i) {
        float2 v = __half22float2(Y[g_col[i] * 32 + lane]);
        sxa[0] += v.x; sya[0] += v.y;
    }
    float sx = ((sxa[0]+sxa[1])+(sxa[2]+sxa[3]))+((sxa[4]+sxa[5])+(sxa[6]+sxa[7]));
    float sy = ((sya[0]+sya[1])+(sya[2]+sya[3]))+((sya[4]+sya[5])+(sya[6]+sya[7]));
    float inv = g_invdeg[node];
    float2 z  = *(const float2*)&g_z2[node * 64 + 2 * lane];
    float2 res;
    res.x = sx * inv + z.x;
    res.y = sy * inv + z.y;
    *(float2*)&Og[node * 64 + 2 * lane] = res;
}

// ------------------------------------------------------------------- launch
extern "C" void kernel_launch(void* const* d_in, const int* in_sizes, int n_in,
                              void* d_out, int out_size) {
    const float* x   = (const float*)d_in[0];
    const int*   ei  = (const int*)d_in[1];
    const float* w1l = (const float*)d_in[2];
    const float* b1l = (const float*)d_in[3];
    const float* w1r = (const float*)d_in[4];
    const float* w2l = (const float*)d_in[5];
    const float* b2l = (const float*)d_in[6];
    const float* w2r = (const float*)d_in[7];
    float* out = (float*)d_out;

    int n = in_sizes[0] / F;
    int E = in_sizes[1] / 2;
    const int* src = ei;
    const int* dst = ei + E;

    int nb1024 = (n + 1023) / 1024;
    int HB = (E + 255) / 256;
    int GB = (n + 63) / 64;

    k_histgemm<<<HB + GB, 256>>>(dst, E, HB, x, w1l, w1r, b1l, n);
    k_scan1   <<<nb1024, 1024>>>(n);
    k_scan23  <<<(n + 255) / 256, 256>>>(n, E, nb1024);
    k_scatter <<<(E + 255) / 256, 256>>>(src, dst, E);

    k_fused <<<GB, 256>>>(w2l, w2r, b2l, n);
    k_agg2  <<<(n + 7) / 8, 256>>>(out, n);
}

// round 9
// speedup vs baseline: 1.5614x; 1.0982x over previous
#include <cuda_runtime.h>
#include <cuda_fp16.h>
#include <cstdint>

// GraphSAGE 2-layer encoder.
//   y = h@Wl (fp16), z = h@Wr + b (fp32), out[i] = inv[i]*sum_{j in N(i)} y[j] + z[i]
// HMMA GEMMs; layer-1 GEMM overlapped with CSR histogram; wide-load gathers.

#define NMAX 100000
#define EMAX 1600000
#define F 64
#define TS 72   // smem row stride in halves (144B, 16B-aligned rows)

__device__ __align__(16) __half g_ya[NMAX * F];
__device__ __align__(16) __half g_yb[NMAX * F];
__device__ __align__(16) float  g_z1[NMAX * F];
__device__ __align__(16) float  g_z2[NMAX * F];
__device__ float g_invdeg[NMAX];
__device__ int   g_cnt[NMAX];        // zero-init at load; re-zeroed by k_agg2
__device__ int   g_rowptr[NMAX];
__device__ int   g_rowend[NMAX];
__device__ int   g_pos[EMAX];
__device__ int   g_col[EMAX];
__device__ int   g_ctr;              // chunk-base counter (re-zeroed by k_agg2)

// ---------------------------------------------------------------- MMA bits
__device__ __forceinline__ unsigned smem_u32(const void* p) {
    return (unsigned)__cvta_generic_to_shared(p);
}
__device__ __forceinline__ void ldsm_x4(unsigned& a0, unsigned& a1,
                                        unsigned& a2, unsigned& a3, unsigned addr) {
    asm volatile("ldmatrix.sync.aligned.m8n8.x4.shared.b16 {%0,%1,%2,%3}, [%4];"
                 : "=r"(a0), "=r"(a1), "=r"(a2), "=r"(a3) : "r"(addr));
}
__device__ __forceinline__ void ldsm_x2t(unsigned& b0, unsigned& b1, unsigned addr) {
    asm volatile("ldmatrix.sync.aligned.m8n8.x2.trans.shared.b16 {%0,%1}, [%2];"
                 : "=r"(b0), "=r"(b1) : "r"(addr));
}
__device__ __forceinline__ void mma16816(float* d, unsigned a0, unsigned a1,
                                         unsigned a2, unsigned a3,
                                         unsigned b0, unsigned b1) {
    asm volatile("mma.sync.aligned.m16n8k16.row.col.f32.f16.f16.f32 "
                 "{%0,%1,%2,%3}, {%4,%5,%6,%7}, {%8,%9}, {%0,%1,%2,%3};"
                 : "+f"(d[0]), "+f"(d[1]), "+f"(d[2]), "+f"(d[3])
                 : "r"(a0), "r"(a1), "r"(a2), "r"(a3), "r"(b0), "r"(b1));
}

// Dual GEMM on a 64-row tile: Y = A@Wl (fp16 out), Z = A@Wr + b (fp32 out).
__device__ __forceinline__ void mma_dual(const __half* xs, const __half* wls,
                                         const __half* wrs, const float* bs,
                                         __half* Yg, float* Zg, int row0, int n,
                                         int tid) {
    int w = tid >> 5, l = tid & 31;
    int m0 = (w & 3) * 16;
    int nb = (w >> 2) * 32;

    float acc0[4][4], acc1[4][4];
    #pragma unroll
    for (int j = 0; j < 4; ++j)
        #pragma unroll
        for (int q = 0; q < 4; ++q) { acc0[j][q] = 0.f; acc1[j][q] = 0.f; }

    int ag = l >> 3, ar = l & 7;
    int arow = m0 + (ag & 1) * 8 + ar;
    int acol = (ag >> 1) * 8;
    int br   = (l & 7) + ((l >> 3) & 1) * 8;

    #pragma unroll
    for (int kc = 0; kc < 4; ++kc) {
        int k0 = kc * 16;
        unsigned a0, a1, a2, a3;
        ldsm_x4(a0, a1, a2, a3, smem_u32(&xs[arow * TS + k0 + acol]));
        #pragma unroll
        for (int j = 0; j < 4; ++j) {
            int n0 = nb + j * 8;
            unsigned b0, b1, c0, c1;
            ldsm_x2t(b0, b1, smem_u32(&wls[(k0 + br) * TS + n0]));
            mma16816(acc0[j], a0, a1, a2, a3, b0, b1);
            ldsm_x2t(c0, c1, smem_u32(&wrs[(k0 + br) * TS + n0]));
            mma16816(acc1[j], a0, a1, a2, a3, c0, c1);
        }
    }

    int tr = l >> 2, tc = (l & 3) * 2;
    #pragma unroll
    for (int j = 0; j < 4; ++j) {
        int gc = nb + j * 8 + tc;
        float bx = bs[gc], by = bs[gc + 1];
        #pragma unroll
        for (int h = 0; h < 2; ++h) {
            int gr = row0 + m0 + tr + h * 8;
            if (gr < n) {
                *(__half2*)&Yg[gr * 64 + gc] =
                    __floats2half2_rn(acc0[j][h * 2], acc0[j][h * 2 + 1]);
                *(float2*)&Zg[gr * 64 + gc] =
                    make_float2(acc1[j][h * 2] + bx, acc1[j][h * 2 + 1] + by);
            }
        }
    }
}

// accumulate 8 halves (one float4) into 8 fp32 accumulators
__device__ __forceinline__ void add8(float* acc, float4 v) {
    __half2* h = (__half2*)&v;
    #pragma unroll
    for (int k = 0; k < 4; ++k) {
        float2 f = __half22float2(h[k]);
        acc[2 * k]     += f.x;
        acc[2 * k + 1] += f.y;
    }
}

// Warp-cooperative gather: lane = (g = l>>3 edge subgroup, s = l&7 dim chunk).
// Each lane loads float4 (16B) of the y-row; 4 edges per warp-step.
// Returns full row sum in acc[8] of lanes with g==0 (after shfl reduce).
__device__ __forceinline__ void gather_row(const float4* Y, int i0, int e,
                                           int g, int s, float* acc) {
    #pragma unroll
    for (int d = 0; d < 8; ++d) acc[d] = 0.f;
    int i = i0 + g;
    for (; i + 12 < e; i += 16) {
        float4 v0 = Y[g_col[i]      * 8 + s];
        float4 v1 = Y[g_col[i + 4]  * 8 + s];
        float4 v2 = Y[g_col[i + 8]  * 8 + s];
        float4 v3 = Y[g_col[i + 12] * 8 + s];
        add8(acc, v0); add8(acc, v1); add8(acc, v2); add8(acc, v3);
    }
    for (; i < e; i += 4) {
        add8(acc, Y[g_col[i] * 8 + s]);
    }
    __syncwarp();
    #pragma unroll
    for (int d = 0; d < 8; ++d) {
        acc[d] += __shfl_xor_sync(0xffffffffu, acc[d], 8);
        acc[d] += __shfl_xor_sync(0xffffffffu, acc[d], 16);
    }
}

// ------------------------------ fused histogram (CSR pass 1) + layer-1 GEMM
__global__ __launch_bounds__(256) void k_histgemm(const int* __restrict__ dst, int E, int HB,
                                                  const float* __restrict__ X,
                                                  const float* __restrict__ Wl,
                                                  const float* __restrict__ Wr,
                                                  const float* __restrict__ B,
                                                  int n) {
    if (blockIdx.x < (unsigned)HB) {
        int t  = blockIdx.x * 256 + threadIdx.x;
        int e4 = t * 4;
        if (e4 >= E) return;
        if (((E & 3) == 0) && e4 + 3 < E) {
            int4 d4 = ((const int4*)dst)[t];
            g_pos[e4 + 0] = atomicAdd(&g_cnt[d4.x], 1);
            g_pos[e4 + 1] = atomicAdd(&g_cnt[d4.y], 1);
            g_pos[e4 + 2] = atomicAdd(&g_cnt[d4.z], 1);
            g_pos[e4 + 3] = atomicAdd(&g_cnt[d4.w], 1);
        } else {
            int lim = min(e4 + 4, E);
            for (int e = e4; e < lim; ++e)
                g_pos[e] = atomicAdd(&g_cnt[dst[e]], 1);
        }
        return;
    }

    __shared__ __half xs[64 * TS];
    __shared__ __half wls[64 * TS];
    __shared__ __half wrs[64 * TS];
    __shared__ float  bs[64];

    int tid  = threadIdx.x;
    int row0 = ((int)blockIdx.x - HB) * 64;

    for (int t = tid; t < 1024; t += 256) {
        int r = t >> 4, c4 = (t & 15) << 2;
        float4 wl = ((const float4*)Wl)[t];
        float4 wr = ((const float4*)Wr)[t];
        *(__half2*)&wls[r * TS + c4]     = __floats2half2_rn(wl.x, wl.y);
        *(__half2*)&wls[r * TS + c4 + 2] = __floats2half2_rn(wl.z, wl.w);
        *(__half2*)&wrs[r * TS + c4]     = __floats2half2_rn(wr.x, wr.y);
        *(__half2*)&wrs[r * TS + c4 + 2] = __floats2half2_rn(wr.z, wr.w);

        int g = row0 + r;
        float4 v = make_float4(0.f, 0.f, 0.f, 0.f);
        if (g < n) v = *(const float4*)&X[g * 64 + c4];
        *(__half2*)&xs[r * TS + c4]     = __floats2half2_rn(v.x, v.y);
        *(__half2*)&xs[r * TS + c4 + 2] = __floats2half2_rn(v.z, v.w);
    }
    if (tid < 64) bs[tid] = B[tid];
    __syncthreads();

    mma_dual(xs, wls, wrs, bs, g_ya, g_z1, row0, n, tid);
}

// single-pass CSR scan: local chunk scan + atomic global base (unordered
// chunk placement; rowend stored so cross-chunk adjacency never needed)
__global__ void k_scan(int n) {
    __shared__ int sh[1024];
    __shared__ int base_sh;
    int tid = threadIdx.x;
    int i = blockIdx.x * 1024 + tid;
    int v = (i < n) ? g_cnt[i] : 0;
    sh[tid] = v;
    __syncthreads();
    #pragma unroll
    for (int off = 1; off < 1024; off <<= 1) {
        int t = (tid >= off) ? sh[tid - off] : 0;
        __syncthreads();
        sh[tid] += t;
        __syncthreads();
    }
    if (tid == 1023) base_sh = atomicAdd(&g_ctr, sh[1023]);
    __syncthreads();
    if (i < n) {
        int base = base_sh;
        int incl = sh[tid];
        g_rowptr[i] = base + incl - v;
        g_rowend[i] = base + incl;
        g_invdeg[i] = 1.0f / (float)max(v, 1);
    }
}

// atomic-free scatter, 4 edges/thread
__global__ void k_scatter(const int* __restrict__ src, const int* __restrict__ dst, int E) {
    int t  = blockIdx.x * blockDim.x + threadIdx.x;
    int e4 = t * 4;
    if (e4 >= E) return;
    if (((E & 3) == 0) && e4 + 3 < E) {
        int4 d4 = ((const int4*)dst)[t];
        int4 p4 = ((const int4*)g_pos)[t];
        int4 s4 = ((const int4*)src)[t];
        g_col[g_rowptr[d4.x] + p4.x] = s4.x;
        g_col[g_rowptr[d4.y] + p4.y] = s4.y;
        g_col[g_rowptr[d4.z] + p4.z] = s4.z;
        g_col[g_rowptr[d4.w] + p4.w] = s4.w;
    } else {
        int lim = min(e4 + 4, E);
        for (int e = e4; e < lim; ++e)
            g_col[g_rowptr[dst[e]] + g_pos[e]] = src[e];
    }
}

// -------------------------------- fused layer-1 aggregate + layer-2 GEMM
__global__ __launch_bounds__(256) void k_fused(const float* __restrict__ Wl,
                                               const float* __restrict__ Wr,
                                               const float* __restrict__ B,
                                               int n) {
    __shared__ __half xs[64 * TS];
    __shared__ __half wls[64 * TS];
    __shared__ __half wrs[64 * TS];
    __shared__ float  bs[64];

    int tid  = threadIdx.x;
    int row0 = blockIdx.x * 64;
    int lane = tid & 31, w = tid >> 5;
    int g = lane >> 3, s = lane & 7;

    for (int t = tid; t < 1024; t += 256) {
        int r = t >> 4, c4 = (t & 15) << 2;
        float4 wl = ((const float4*)Wl)[t];
        float4 wr = ((const float4*)Wr)[t];
        *(__half2*)&wls[r * TS + c4]     = __floats2half2_rn(wl.x, wl.y);
        *(__half2*)&wls[r * TS + c4 + 2] = __floats2half2_rn(wl.z, wl.w);
        *(__half2*)&wrs[r * TS + c4]     = __floats2half2_rn(wr.x, wr.y);
        *(__half2*)&wrs[r * TS + c4 + 2] = __floats2half2_rn(wr.z, wr.w);
    }
    if (tid < 64) bs[tid] = B[tid];

    // phase 1: warp per node; 8 passes cover 64 rows
    const float4* Y = (const float4*)g_ya;
    #pragma unroll 1
    for (int pass = 0; pass < 8; ++pass) {
        int nl   = pass * 8 + w;
        int node = row0 + nl;
        float acc[8];
        int i0 = 0, e = 0;
        if (node < n) { i0 = g_rowptr[node]; e = g_rowend[node]; }
        gather_row(Y, i0, e, g, s, acc);
        if (g == 0) {
            __half2 hh[4];
            if (node < n) {
                float inv = g_invdeg[node];
                const float4* Z = (const float4*)g_z1;
                float4 z0 = Z[node * 16 + s * 2];
                float4 z1 = Z[node * 16 + s * 2 + 1];
                hh[0] = __floats2half2_rn(fmaxf(acc[0]*inv + z0.x, 0.f),
                                          fmaxf(acc[1]*inv + z0.y, 0.f));
                hh[1] = __floats2half2_rn(fmaxf(acc[2]*inv + z0.z, 0.f),
                                          fmaxf(acc[3]*inv + z0.w, 0.f));
                hh[2] = __floats2half2_rn(fmaxf(acc[4]*inv + z1.x, 0.f),
                                          fmaxf(acc[5]*inv + z1.y, 0.f));
                hh[3] = __floats2half2_rn(fmaxf(acc[6]*inv + z1.z, 0.f),
                                          fmaxf(acc[7]*inv + z1.w, 0.f));
            } else {
                hh[0] = hh[1] = hh[2] = hh[3] = __floats2half2_rn(0.f, 0.f);
            }
            *(float4*)&xs[nl * TS + s * 8] = *(float4*)hh;
        }
    }
    __syncthreads();

    mma_dual(xs, wls, wrs, bs, g_yb, g_z2, row0, n, tid);
}

// --------------------------------------------------------- final aggregate
__global__ __launch_bounds__(256) void k_agg2(float* __restrict__ Og, int n) {
    int tid  = threadIdx.x;
    int lane = tid & 31, w = tid >> 5;
    int node = blockIdx.x * 8 + w;
    int g = lane >> 3, s = lane & 7;

    if (tid < 8) {
        int nn = blockIdx.x * 8 + tid;
        if (nn < n) g_cnt[nn] = 0;      // counters clean for next graph replay
    }
    if (blockIdx.x == 0 && tid == 0) g_ctr = 0;
    if (node >= n) return;

    const float4* Y = (const float4*)g_yb;
    float acc[8];
    gather_row(Y, g_rowptr[node], g_rowend[node], g, s, acc);

    if (g == 0) {
        float inv = g_invdeg[node];
        const float4* Z = (const float4*)g_z2;
        float4 z0 = Z[node * 16 + s * 2];
        float4 z1 = Z[node * 16 + s * 2 + 1];
        float4 o0 = make_float4(acc[0]*inv + z0.x, acc[1]*inv + z0.y,
                                acc[2]*inv + z0.z, acc[3]*inv + z0.w);
        float4 o1 = make_float4(acc[4]*inv + z1.x, acc[5]*inv + z1.y,
                                acc[6]*inv + z1.z, acc[7]*inv + z1.w);
        *(float4*)&Og[node * 64 + s * 8]     = o0;
        *(float4*)&Og[node * 64 + s * 8 + 4] = o1;
    }
}

// ------------------------------------------------------------------- launch
extern "C" void kernel_launch(void* const* d_in, const int* in_sizes, int n_in,
                              void* d_out, int out_size) {
    const float* x   = (const float*)d_in[0];
    const int*   ei  = (const int*)d_in[1];
    const float* w1l = (const float*)d_in[2];
    const float* b1l = (const float*)d_in[3];
    const float* w1r = (const float*)d_in[4];
    const float* w2l = (const float*)d_in[5];
    const float* b2l = (const float*)d_in[6];
    const float* w2r = (const float*)d_in[7];
    float* out = (float*)d_out;

    int n = in_sizes[0] / F;
    int E = in_sizes[1] / 2;
    const int* src = ei;
    const int* dst = ei + E;

    int HB = (E + 1023) / 1024;          // hist blocks (4 edges/thread)
    int GB = (n + 63) / 64;              // gemm blocks

    k_histgemm<<<HB + GB, 256>>>(dst, E, HB, x, w1l, w1r, b1l, n);
    k_scan    <<<(n + 1023) / 1024, 1024>>>(n);
    k_scatter <<<(E / 4 + 255) / 256, 256>>>(src, dst, E);

    k_fused <<<GB, 256>>>(w2l, w2r, b2l, n);
    k_agg2  <<<(n + 7) / 8, 256>>>(out, n);
}